// round 16
// baseline (speedup 1.0000x reference)
#include <cuda_runtime.h>
#include <cuda_fp16.h>
#include <cuda_bf16.h>
#include <math.h>
#include <stdint.h>

#define BATCH   8
#define NN      64
#define KTOT    65536
#define SPLITS  32
#define KCH     (KTOT / SPLITS)   // 2048
#define TILE_K  128               // floats per tile row (512B bursts)
#define NTILES  (KCH / TILE_K)    // 16
#define HSTRIDE 136               // fp16 smem row stride (272B)
#define ITERS   10
#define NTHREADS 448              // 10 consumer warps + 4 producer warps

// Gram scratch [B][N][N]; zero at module load, re-zeroed by crf_kernel.
__device__ float g_gram[BATCH * NN * NN];

__device__ __forceinline__ uint32_t smem_u32(const void* p) {
    return (uint32_t)__cvta_generic_to_shared(p);
}

#define BAR_SYNC(id)   asm volatile("bar.sync %0, 448;"   :: "r"(id) : "memory")
#define BAR_ARRIVE(id) asm volatile("bar.arrive %0, 448;" :: "r"(id) : "memory")

// ---------------------------------------------------------------------------
// Kernel 1: warp-specialized split-K Gram, UPPER-TRIANGLE-ONLY consumers.
// grid = (SPLITS, BATCH) = 256 CTAs, block = 448, occ 2 -> single wave.
// Producer warps 10-13: R12 path (512B row bursts, LDG->cvt->STS).
// Consumer warps 0-9: 2 upper-tri 16x8 tiles each (R5 validated map);
// off-diagonal tiles mirrored into [j,i] in the epilogue.
// ---------------------------------------------------------------------------
__global__ void __launch_bounds__(NTHREADS, 2) gram_mma_kernel(const float* __restrict__ feats) {
    __shared__ __align__(16) __half hbuf[2][64 * HSTRIDE];   // 2 x 17 KB

    const int tid  = threadIdx.x;
    const int wid  = tid >> 5;
    const int lane = tid & 31;

    const int b = blockIdx.y;
    const int s = blockIdx.x;
    const float* base = feats + (size_t)b * NN * KTOT + (size_t)s * KCH;

    if (wid >= 10) {
        // -------- producer warps (4): rows [16*pw, 16*pw+16) --------
        const int pw = wid - 10;
        const int rbase = pw * 16;
        for (int t = 0; t < NTILES; ++t) {
            const int buf = t & 1;
            if (t >= 2) BAR_SYNC(3 + buf);          // consumers done with buf
            const float* g = base + t * TILE_K;
#pragma unroll
            for (int h = 0; h < 2; ++h) {
                float4 v[8];
#pragma unroll
                for (int i = 0; i < 8; ++i) {
                    const int row = rbase + h * 8 + i;
                    v[i] = *reinterpret_cast<const float4*>(g + (size_t)row * KTOT + lane * 4);
                }
#pragma unroll
                for (int i = 0; i < 8; ++i) {
                    const int row = rbase + h * 8 + i;
                    __half2 h0 = __float22half2_rn(make_float2(v[i].x, v[i].y));
                    __half2 h1 = __float22half2_rn(make_float2(v[i].z, v[i].w));
                    uint2 w = make_uint2(*(uint32_t*)&h0, *(uint32_t*)&h1);
                    *reinterpret_cast<uint2*>(&hbuf[buf][row * HSTRIDE + lane * 4]) = w;
                }
            }
            BAR_ARRIVE(1 + buf);                    // buf full
        }
        return;                                     // producers exit
    }

    // -------- consumer warps (10): upper-tri 16x16 block each --------
    // wr  = {0,0,0,0,1,1,1,2,2,3}; wc16 = {0,1,2,3,1,2,3,2,3,3}
    const uint64_t WRP = 0x3221110000ULL;
    const uint64_t WCP = 0x3323213210ULL;
    const int r  = (int)((WRP >> (wid * 4)) & 0xF);
    const int cb = (int)((WCP >> (wid * 4)) & 0xF) * 16;
    const int tg = lane & 3;

    const int a_row  = 16 * r + (lane & 7) + ((lane >> 3) & 1) * 8;
    const int a_koff = (lane >> 4) * 8;
    const int b_col  = cb + (lane & 7) + ((lane >> 4) & 1) * 8;
    const int b_koff = ((lane >> 3) & 1) * 8;

    float acc[2][4];
#pragma unroll
    for (int i = 0; i < 2; ++i)
#pragma unroll
        for (int j = 0; j < 4; ++j) acc[i][j] = 0.0f;

    for (int t = 0; t < NTILES; ++t) {
        const int buf = t & 1;
        BAR_SYNC(1 + buf);                          // wait buf full

        const __half* S = &hbuf[buf][0];
#pragma unroll
        for (int kk = 0; kk < 8; ++kk) {
            const int k0 = kk * 16;
            uint32_t a0, a1, a2, a3, b01[2], b23[2];
            {
                uint32_t addr = smem_u32(S + a_row * HSTRIDE + k0 + a_koff);
                asm volatile("ldmatrix.sync.aligned.m8n8.x4.shared.b16 {%0,%1,%2,%3}, [%4];"
                             : "=r"(a0), "=r"(a1), "=r"(a2), "=r"(a3) : "r"(addr));
            }
            {
                uint32_t addr = smem_u32(S + b_col * HSTRIDE + k0 + b_koff);
                asm volatile("ldmatrix.sync.aligned.m8n8.x4.shared.b16 {%0,%1,%2,%3}, [%4];"
                             : "=r"(b01[0]), "=r"(b01[1]), "=r"(b23[0]), "=r"(b23[1]) : "r"(addr));
            }
#define MMA16(accv, bb)                                                         \
    asm volatile("mma.sync.aligned.m16n8k16.row.col.f32.f16.f16.f32 "          \
                 "{%0,%1,%2,%3}, {%4,%5,%6,%7}, {%8,%9}, {%0,%1,%2,%3};"       \
                 : "+f"(accv[0]), "+f"(accv[1]), "+f"(accv[2]), "+f"(accv[3])  \
                 : "r"(a0), "r"(a1), "r"(a2), "r"(a3), "r"(bb[0]), "r"(bb[1]))
            MMA16(acc[0], b01);
            MMA16(acc[1], b23);
#undef MMA16
        }
        BAR_ARRIVE(3 + buf);                        // buf empty
    }

    // epilogue: direct writes + mirror for off-diagonal tiles (R5 validated)
    float* gb = g_gram + (size_t)b * NN * NN;
    const int r0 = 16 * r + (lane >> 2);
#pragma unroll
    for (int nt = 0; nt < 2; ++nt) {
        const int col   = cb + nt * 8 + tg * 2;
        const int ctile = (cb >> 3) + nt;
        const bool diag = ((ctile >> 1) == r);
        atomicAdd(&gb[(r0)     * NN + col    ], acc[nt][0]);
        atomicAdd(&gb[(r0)     * NN + col + 1], acc[nt][1]);
        atomicAdd(&gb[(r0 + 8) * NN + col    ], acc[nt][2]);
        atomicAdd(&gb[(r0 + 8) * NN + col + 1], acc[nt][3]);
        if (!diag) {
            atomicAdd(&gb[(col)     * NN + r0    ], acc[nt][0]);
            atomicAdd(&gb[(col + 1) * NN + r0    ], acc[nt][1]);
            atomicAdd(&gb[(col)     * NN + r0 + 8], acc[nt][2]);
            atomicAdd(&gb[(col + 1) * NN + r0 + 8], acc[nt][3]);
        }
    }
}

// ---------------------------------------------------------------------------
// Kernel 2: CRF iterations + output. grid = BATCH, block = 256.
// tanh addition identity: tanh((li+ej)/2) = (ti+uj)/(1+ti*uj) with
// ti = tanh(li/2) (once), uj = tanh(ej/2) carried across iterations.
// -> 1 MUFU (rcp) per pair instead of 2. Also re-zeroes g_gram.
// ---------------------------------------------------------------------------
__global__ void __launch_bounds__(256) crf_kernel(const float* __restrict__ logits,
                                                  const float* __restrict__ W,
                                                  float* __restrict__ out) {
    const int b   = blockIdx.x;
    const int tid = threadIdx.x;
    const int i   = tid >> 2;
    const int q   = tid & 3;
    const int j0  = q * 16;

    __shared__ float nrm[64];
    __shared__ float lg[64];
    __shared__ float ubuf[2][64];   // u = tanh(e/2)
    __shared__ float efin[64];      // e of final iteration
    __shared__ float red[64];

    float* gb = g_gram + (size_t)b * NN * NN;

    if (tid < 64) {
        nrm[tid] = sqrtf(gb[tid * NN + tid]);
        lg[tid]  = logits[b * NN + tid];
        ubuf[0][tid] = 0.0f;        // e0 = 0 -> u0 = 0
    }
    __syncthreads();

    const float ni = nrm[i];
    float pp[16];
#pragma unroll
    for (int jj = 0; jj < 16; ++jj) {
        const int j = j0 + jj;
        const float dot  = gb[i * NN + j];
        const float sim  = dot / (ni * nrm[j] + 1e-6f);
        const float wsym = 0.5f * (W[i * NN + j] + W[j * NN + i]);
        pp[jj] = sim * wsym;
    }
#pragma unroll
    for (int jj = 0; jj < 16; jj += 4)
        *reinterpret_cast<float4*>(&gb[i * NN + j0 + jj]) = make_float4(0.f, 0.f, 0.f, 0.f);

    const float li = lg[i];
    // ti = tanh(li/2) = (1 - e^-li) / (1 + e^-li)
    float ti;
    {
        float t, rr;
        asm("ex2.approx.f32 %0, %1;" : "=f"(t) : "f"(li * -1.4426950408889634f));
        asm("rcp.approx.f32 %0, %1;" : "=f"(rr) : "f"(1.0f + t));
        ti = (1.0f - t) * rr;
    }

    int cur = 0;
    for (int it = 0; it < ITERS; ++it) {
        float acc = 0.0f;
        const float* u = ubuf[cur];
#pragma unroll
        for (int jj = 0; jj < 16; ++jj) {
            const float uj = u[j0 + jj];
            const float d  = fmaf(ti, uj, 1.0f);      // in (0, 2): safe
            float rr;
            asm("rcp.approx.f32 %0, %1;" : "=f"(rr) : "f"(d));
            acc = fmaf((ti + uj) * rr, pp[jj], acc);  // tanh((li+ej)/2) * pp
        }
        acc += __shfl_xor_sync(0xFFFFFFFF, acc, 1);
        acc += __shfl_xor_sync(0xFFFFFFFF, acc, 2);
        if (q == 0) {
            // u' = tanh(acc/2)
            float t, rr;
            asm("ex2.approx.f32 %0, %1;" : "=f"(t) : "f"(acc * -1.4426950408889634f));
            asm("rcp.approx.f32 %0, %1;" : "=f"(rr) : "f"(1.0f + t));
            ubuf[cur ^ 1][i] = (1.0f - t) * rr;
            if (it == ITERS - 1) efin[i] = acc;
        }
        __syncthreads();
        cur ^= 1;
    }

    if (tid < 64) red[tid] = efin[tid];
    __syncthreads();
    if (tid < 32) {
        float v = red[tid] + red[tid + 32];
        v += __shfl_xor_sync(0xFFFFFFFF, v, 16);
        v += __shfl_xor_sync(0xFFFFFFFF, v, 8);
        v += __shfl_xor_sync(0xFFFFFFFF, v, 4);
        v += __shfl_xor_sync(0xFFFFFFFF, v, 2);
        v += __shfl_xor_sync(0xFFFFFFFF, v, 1);
        if (tid == 0) red[0] = v;
    }
    __syncthreads();
    if (tid < 64) {
        const float meanE = red[0] * (1.0f / 64.0f);
        out[b * NN + tid] = lg[tid] + meanE;
    }
}

extern "C" void kernel_launch(void* const* d_in, const int* in_sizes, int n_in,
                              void* d_out, int out_size) {
    const float* a_inter = (const float*)d_in[0];  // [8,64,64,32,32]
    const float* logits  = (const float*)d_in[1];  // [8,64]
    const float* W       = (const float*)d_in[2];  // [1,64,64]
    float* out           = (float*)d_out;          // [8,64]

    dim3 grid(SPLITS, BATCH);
    gram_mma_kernel<<<grid, NTHREADS>>>(a_inter);

    crf_kernel<<<BATCH, 256>>>(logits, W, out);
}

// round 17
// speedup vs baseline: 1.1041x; 1.1041x over previous
#include <cuda_runtime.h>
#include <cuda_fp16.h>
#include <cuda_bf16.h>
#include <math.h>
#include <stdint.h>

#define BATCH    8
#define NN       64
#define KTOT     65536
#define SPLITS   37               // CTAs per batch -> 296 CTAs = 2 per SM exactly
#define TILE_K   128              // floats per tile row (512B bursts)
#define TILES_PB 512              // K-tiles per batch (KTOT / TILE_K)
#define HSTRIDE  136              // fp16 smem row stride (272B)
#define ITERS    10
#define NTHREADS 384              // 8 consumer + 4 producer warps

// Gram scratch [B][N][N]; zero at module load, re-zeroed by crf_kernel.
__device__ float g_gram[BATCH * NN * NN];

__device__ __forceinline__ uint32_t smem_u32(const void* p) {
    return (uint32_t)__cvta_generic_to_shared(p);
}

#define BAR_SYNC(id)   asm volatile("bar.sync %0, 384;"   :: "r"(id) : "memory")
#define BAR_ARRIVE(id) asm volatile("bar.arrive %0, 384;" :: "r"(id) : "memory")

// ---------------------------------------------------------------------------
// Kernel 1: warp-specialized split-K Gram (R12 inner code), BALANCED split.
// grid = (37, 8) = 296 CTAs, block 384, occ 2 -> exactly 2 CTAs on every SM.
// Non-uniform K ranges: CTAs 0-30 get 14 tiles, 31-36 get 13 (sum 512).
// Max per-SM load drops 32 -> 28 tiles (balanced optimum 27.7).
// ---------------------------------------------------------------------------
__global__ void __launch_bounds__(NTHREADS, 2) gram_mma_kernel(const float* __restrict__ feats) {
    __shared__ __align__(16) __half hbuf[2][64 * HSTRIDE];   // 2 x 17 KB

    const int tid  = threadIdx.x;
    const int wid  = tid >> 5;
    const int lane = tid & 31;

    const int b = blockIdx.y;
    const int s = blockIdx.x;

    // non-uniform K split: 31 CTAs x 14 tiles + 6 CTAs x 13 tiles = 512
    const int ntiles = (s < 31) ? 14 : 13;
    const int start  = (s < 31) ? s * 14 : 31 * 14 + (s - 31) * 13;
    const float* base = feats + (size_t)b * NN * KTOT + (size_t)start * TILE_K;

    if (wid >= 8) {
        // -------- producer warps (4): rows [16*pw, 16*pw+16) --------
        const int pw = wid - 8;
        const int rbase = pw * 16;
        for (int t = 0; t < ntiles; ++t) {
            const int buf = t & 1;
            if (t >= 2) BAR_SYNC(3 + buf);          // consumers done with buf
            const float* g = base + (size_t)t * TILE_K;
#pragma unroll
            for (int h = 0; h < 2; ++h) {
                float4 v[8];
#pragma unroll
                for (int i = 0; i < 8; ++i) {
                    const int row = rbase + h * 8 + i;
                    v[i] = *reinterpret_cast<const float4*>(g + (size_t)row * KTOT + lane * 4);
                }
#pragma unroll
                for (int i = 0; i < 8; ++i) {
                    const int row = rbase + h * 8 + i;
                    __half2 h0 = __float22half2_rn(make_float2(v[i].x, v[i].y));
                    __half2 h1 = __float22half2_rn(make_float2(v[i].z, v[i].w));
                    uint2 w = make_uint2(*(uint32_t*)&h0, *(uint32_t*)&h1);
                    *reinterpret_cast<uint2*>(&hbuf[buf][row * HSTRIDE + lane * 4]) = w;
                }
            }
            BAR_ARRIVE(1 + buf);                    // buf full
        }
        return;                                     // producers exit
    }

    // -------- consumer warps (8): 4(M) x 2(N) mma layout --------
    const int tg = lane & 3;
    const int wm = wid >> 1;
    const int wn = wid & 1;

    const int a_row  = wm * 16 + (lane & 7) + ((lane >> 3) & 1) * 8;
    const int a_koff = (lane >> 4) * 8;
    const int b_col  = wn * 32 + (lane & 7) + ((lane >> 4) & 1) * 8;
    const int b_koff = ((lane >> 3) & 1) * 8;

    float c[4][4];
#pragma unroll
    for (int i = 0; i < 4; ++i)
#pragma unroll
        for (int j = 0; j < 4; ++j) c[i][j] = 0.0f;

    for (int t = 0; t < ntiles; ++t) {
        const int buf = t & 1;
        BAR_SYNC(1 + buf);                          // wait buf full

        const __half* S = &hbuf[buf][0];
#pragma unroll
        for (int kk = 0; kk < 8; ++kk) {
            const int k0 = kk * 16;
            uint32_t a0, a1, a2, a3, b01[2], b23[2], b45[2], b67[2];
            {
                uint32_t addr = smem_u32(S + a_row * HSTRIDE + k0 + a_koff);
                asm volatile("ldmatrix.sync.aligned.m8n8.x4.shared.b16 {%0,%1,%2,%3}, [%4];"
                             : "=r"(a0), "=r"(a1), "=r"(a2), "=r"(a3) : "r"(addr));
            }
            {
                uint32_t addr = smem_u32(S + b_col * HSTRIDE + k0 + b_koff);
                asm volatile("ldmatrix.sync.aligned.m8n8.x4.shared.b16 {%0,%1,%2,%3}, [%4];"
                             : "=r"(b01[0]), "=r"(b01[1]), "=r"(b23[0]), "=r"(b23[1]) : "r"(addr));
            }
            {
                uint32_t addr = smem_u32(S + (b_col + 16) * HSTRIDE + k0 + b_koff);
                asm volatile("ldmatrix.sync.aligned.m8n8.x4.shared.b16 {%0,%1,%2,%3}, [%4];"
                             : "=r"(b45[0]), "=r"(b45[1]), "=r"(b67[0]), "=r"(b67[1]) : "r"(addr));
            }
#define MMA16(accv, bb)                                                         \
    asm volatile("mma.sync.aligned.m16n8k16.row.col.f32.f16.f16.f32 "          \
                 "{%0,%1,%2,%3}, {%4,%5,%6,%7}, {%8,%9}, {%0,%1,%2,%3};"       \
                 : "+f"(accv[0]), "+f"(accv[1]), "+f"(accv[2]), "+f"(accv[3])  \
                 : "r"(a0), "r"(a1), "r"(a2), "r"(a3), "r"(bb[0]), "r"(bb[1]))
            MMA16(c[0], b01);
            MMA16(c[1], b23);
            MMA16(c[2], b45);
            MMA16(c[3], b67);
#undef MMA16
        }
        BAR_ARRIVE(3 + buf);                        // buf empty
    }

    // epilogue: atomic-accumulate partial C into g_gram[b]
    float* gb = g_gram + (size_t)b * NN * NN;
    const int re = wm * 16 + (lane >> 2);
#pragma unroll
    for (int nt = 0; nt < 4; ++nt) {
        const int col = wn * 32 + nt * 8 + tg * 2;
        atomicAdd(&gb[(re)     * NN + col    ], c[nt][0]);
        atomicAdd(&gb[(re)     * NN + col + 1], c[nt][1]);
        atomicAdd(&gb[(re + 8) * NN + col    ], c[nt][2]);
        atomicAdd(&gb[(re + 8) * NN + col + 1], c[nt][3]);
    }
}

// ---------------------------------------------------------------------------
// Kernel 2: CRF iterations + output (R7/R9 scheme). grid = BATCH, block = 256.
// Also re-zeroes g_gram for the next graph replay.
// ---------------------------------------------------------------------------
__global__ void __launch_bounds__(256) crf_kernel(const float* __restrict__ logits,
                                                  const float* __restrict__ W,
                                                  float* __restrict__ out) {
    const int b   = blockIdx.x;
    const int tid = threadIdx.x;
    const int i   = tid >> 2;
    const int q   = tid & 3;
    const int j0  = q * 16;

    __shared__ float nrm[64];
    __shared__ float lg[64];
    __shared__ float ebuf[2][64];
    __shared__ float red[64];

    float* gb = g_gram + (size_t)b * NN * NN;

    if (tid < 64) {
        nrm[tid] = sqrtf(gb[tid * NN + tid]);
        lg[tid]  = logits[b * NN + tid];
        ebuf[0][tid] = 0.0f;
    }
    __syncthreads();

    const float ni = nrm[i];
    float pp[16];
#pragma unroll
    for (int jj = 0; jj < 16; ++jj) {
        const int j = j0 + jj;
        const float dot  = gb[i * NN + j];
        const float sim  = dot / (ni * nrm[j] + 1e-6f);
        const float wsym = 0.5f * (W[i * NN + j] + W[j * NN + i]);
        pp[jj] = sim * wsym;
    }
#pragma unroll
    for (int jj = 0; jj < 16; jj += 4)
        *reinterpret_cast<float4*>(&gb[i * NN + j0 + jj]) = make_float4(0.f, 0.f, 0.f, 0.f);

    const float li = lg[i];
    int cur = 0;
    for (int it = 0; it < ITERS; ++it) {
        float acc = 0.0f;
        const float* e = ebuf[cur];
#pragma unroll
        for (int jj = 0; jj < 16; ++jj) {
            const float x = li + e[j0 + jj];
            float t, r;
            asm("ex2.approx.f32 %0, %1;" : "=f"(t) : "f"(x * -1.4426950408889634f));
            asm("rcp.approx.f32 %0, %1;" : "=f"(r) : "f"(1.0f + t));
            acc = fmaf((1.0f - t) * r, pp[jj], acc);
        }
        acc += __shfl_xor_sync(0xFFFFFFFF, acc, 1);
        acc += __shfl_xor_sync(0xFFFFFFFF, acc, 2);
        if (q == 0) ebuf[cur ^ 1][i] = acc;
        __syncthreads();
        cur ^= 1;
    }

    if (tid < 64) red[tid] = ebuf[cur][tid];
    __syncthreads();
    if (tid < 32) {
        float v = red[tid] + red[tid + 32];
        v += __shfl_xor_sync(0xFFFFFFFF, v, 16);
        v += __shfl_xor_sync(0xFFFFFFFF, v, 8);
        v += __shfl_xor_sync(0xFFFFFFFF, v, 4);
        v += __shfl_xor_sync(0xFFFFFFFF, v, 2);
        v += __shfl_xor_sync(0xFFFFFFFF, v, 1);
        if (tid == 0) red[0] = v;
    }
    __syncthreads();
    if (tid < 64) {
        const float meanE = red[0] * (1.0f / 64.0f);
        out[b * NN + tid] = lg[tid] + meanE;
    }
}

extern "C" void kernel_launch(void* const* d_in, const int* in_sizes, int n_in,
                              void* d_out, int out_size) {
    const float* a_inter = (const float*)d_in[0];  // [8,64,64,32,32]
    const float* logits  = (const float*)d_in[1];  // [8,64]
    const float* W       = (const float*)d_in[2];  // [1,64,64]
    float* out           = (float*)d_out;          // [8,64]

    dim3 grid(SPLITS, BATCH);
    gram_mma_kernel<<<grid, NTHREADS>>>(a_inter);

    crf_kernel<<<BATCH, 256>>>(logits, W, out);
}